// round 14
// baseline (speedup 1.0000x reference)
#include <cuda_runtime.h>
#include <cuda_bf16.h>

// ---- model constants ----
#define BB 2
#define SS 2048
#define DD 1024
#define NLAY 8
#define NV1 200
#define NV2 160
#define NCH 256       // scan chunks over S
#define TC 8          // timesteps per chunk (NCH*TC == SS)
#define NROWS (BB*SS) // 4096
#define EPSF 1e-6f
#define FLAGN (BB*NCH)

typedef unsigned long long ull;

// ---- device scratch (no allocations allowed) ----
__device__ float g_X[NROWS * DD];          // activations
__device__ float g_R[NROWS];               // rmsnorm factors (current layer)
__device__ float g_HLOCp[2][FLAGN * DD];   // per-chunk local aggregates, parity by layer
__device__ float g_HIN[FLAGN * DD];        // inclusive prefixes (per layer, overwritten)
__device__ unsigned g_aflag[2][FLAGN];     // aggregate-ready flags (parity by layer)
__device__ unsigned g_pflag[FLAGN];        // prefix-ready flags
__device__ unsigned g_epoch;               // bumped once per kernel_launch

// ---- f32x2 packed-math helpers ----
__device__ __forceinline__ ull pack2(float lo, float hi) {
    ull r; asm("mov.b64 %0, {%1, %2};" : "=l"(r) : "f"(lo), "f"(hi)); return r;
}
__device__ __forceinline__ void unpack2(ull v, float& lo, float& hi) {
    asm("mov.b64 {%0, %1}, %2;" : "=f"(lo), "=f"(hi) : "l"(v));
}
__device__ __forceinline__ ull ffma2(ull a, ull b, ull c) {
    ull d; asm("fma.rn.f32x2 %0, %1, %2, %3;" : "=l"(d) : "l"(a), "l"(b), "l"(c)); return d;
}

__device__ __forceinline__ float sigmoidf_acc(float x) { return 1.f / (1.f + expf(-x)); }

// jax.nn.gelu default = tanh approximation
__device__ __forceinline__ float geluf(float x) {
    float x3 = x * x * x;
    return 0.5f * x * (1.f + tanhf(0.7978845608028654f * (x + 0.044715f * x3)));
}

// 5-wide block reduce with broadcast; sbuf >= 48 floats (256 threads)
__device__ __forceinline__ void blockReduce5(float* p, float* sbuf) {
    int lane = threadIdx.x & 31, w = threadIdx.x >> 5;
    #pragma unroll
    for (int o = 16; o > 0; o >>= 1) {
        #pragma unroll
        for (int j = 0; j < 5; j++) p[j] += __shfl_down_sync(0xffffffffu, p[j], o);
    }
    if (lane == 0) {
        #pragma unroll
        for (int j = 0; j < 5; j++) sbuf[w * 5 + j] = p[j];
    }
    __syncthreads();
    if (w == 0) {
        float q[5];
        #pragma unroll
        for (int j = 0; j < 5; j++) q[j] = (lane < 8) ? sbuf[lane * 5 + j] : 0.f;
        #pragma unroll
        for (int o = 4; o > 0; o >>= 1) {
            #pragma unroll
            for (int j = 0; j < 5; j++) q[j] += __shfl_down_sync(0xffffffffu, q[j], o);
        }
        if (lane == 0) {
            #pragma unroll
            for (int j = 0; j < 5; j++) sbuf[40 + j] = q[j];
        }
    }
    __syncthreads();
    #pragma unroll
    for (int j = 0; j < 5; j++) p[j] = sbuf[40 + j];
}

// ============================================================
// 0) epoch bump (once per kernel_launch; makes flag targets replay-fresh)
// ============================================================
__global__ void k_epoch() { g_epoch = g_epoch + 1u; }

// ============================================================
// 1) fused embed: TT embedding + rmsnorm + layer-0 partial scan -> HLOC par 0
// ============================================================
__global__ void __launch_bounds__(256) k_embed_fused(
        const int* __restrict__ ids,
        const float* __restrict__ c1,
        const float* __restrict__ c2,
        const float* __restrict__ lam0,
        const float* __restrict__ vv0,
        const float* __restrict__ n1w0) {
    __shared__ float s1[TC][32], s2[TC][32];
    __shared__ float sW[TC * 8];
    __shared__ float sR[TC];
    int blk = blockIdx.x; int b = blk >> 8; int ch = blk & (NCH - 1);
    int tid = threadIdx.x, lane = tid & 31, w = tid >> 5;
    int row0 = b * SS + ch * TC;
    int myIdx = b * NCH + ch;
    unsigned ep = *(volatile unsigned*)&g_epoch;

    float a[4], vi[4], N1[4];
    #pragma unroll
    for (int q = 0; q < 4; q++) {
        int c = tid + q * 256;
        a[q] = sigmoidf_acc(lam0[c]); vi[q] = vv0[c]; N1[q] = n1w0[c];
    }

    for (int i = tid; i < TC * 64; i += 256) {
        int t = i >> 6, j = i & 63;
        int id = ids[row0 + t];
        if (j < 32) s1[t][j] = c1[(id / NV2) * 32 + j];
        else        s2[t][j - 32] = c2[(id % NV2) * 32 + (j - 32)];
    }
    __syncthreads();

    float x[TC][4];
    #pragma unroll
    for (int t = 0; t < TC; t++) {
        float s = 0.f;
        #pragma unroll
        for (int q = 0; q < 4; q++) {
            int d = tid + q * 256;
            x[t][q] = s1[t][d >> 5] * s2[t][d & 31];
            s += x[t][q] * x[t][q];
        }
        #pragma unroll
        for (int o = 16; o > 0; o >>= 1) s += __shfl_down_sync(0xffffffffu, s, o);
        if (lane == 0) sW[t * 8 + w] = s;
        float* xr = g_X + (size_t)(row0 + t) * DD;
        #pragma unroll
        for (int q = 0; q < 4; q++) xr[tid + q * 256] = x[t][q];
    }
    __syncthreads();

    {
        float s = (lane < 8) ? sW[w * 8 + lane] : 0.f;
        #pragma unroll
        for (int o = 4; o > 0; o >>= 1) s += __shfl_down_sync(0xffffffffu, s, o);
        float tot = __shfl_sync(0xffffffffu, s, 0);
        float r = rsqrtf(tot * (1.f / (float)DD) + EPSF);
        if (lane == 0) { sR[w] = r; g_R[row0 + w] = r; }
    }
    __syncthreads();

    // layer-0 partial scan (h0 = 0) -> HLOC parity 0 + aggregate flag
    float h[4] = {0.f, 0.f, 0.f, 0.f};
    #pragma unroll
    for (int t = 0; t < TC; t++) {
        float r = sR[t];
        #pragma unroll
        for (int q = 0; q < 4; q++) {
            float z = x[t][q] * r * N1[q];
            h[q] = a[q] * h[q] + vi[q] * z;
        }
    }
    #pragma unroll
    for (int q = 0; q < 4; q++)
        g_HLOCp[0][(size_t)myIdx * DD + tid + q * 256] = h[q];
    __syncthreads();
    if (tid == 0) {
        __threadfence();
        *(volatile unsigned*)&g_aflag[0][myIdx] = ep * (NLAY + 2) + 1u;  // V_a(0)
    }
}

// ============================================================
// 2) fused layer kernel with DECOUPLED LOOK-BACK combine:
//    head: compute h_in(ch) from predecessors' prefixes/aggregates, publish
//          inclusive prefix; then scan-apply + FFN + next-layer rms +
//          next-layer partial scan (-> HLOC parity (l+1)&1).
// ============================================================
__global__ void __launch_bounds__(256) k_fused(
        const float* __restrict__ lam, const float* __restrict__ vv,
        const float* __restrict__ uu,  const float* __restrict__ n1w,
        const float* __restrict__ n2w, const float* __restrict__ w1,
        const float* __restrict__ w2,
        const float* __restrict__ lam_n, const float* __restrict__ vv_n,
        const float* __restrict__ n1w_n, int l, int last) {
    __shared__ float sbuf[48];
    __shared__ float sW[TC * 8 * 5];
    __shared__ float sS[TC * 4];
    __shared__ int s_mode;
    int blk = blockIdx.x; int b = blk >> 8; int ch = blk & (NCH - 1);
    int tid = threadIdx.x, lane = tid & 31, w = tid >> 5;
    int myIdx = b * NCH + ch;
    int row0 = b * SS + ch * TC;
    int p = l & 1, pn = (l + 1) & 1;
    unsigned ep = *(volatile unsigned*)&g_epoch;
    unsigned Vt  = ep * (NLAY + 2) + (unsigned)l + 1u;   // target for layer l flags
    unsigned Vtn = Vt + 1u;                              // for layer l+1 aggregate flag

    float a[4], vi[4], uo[4], N1[4], N2[4], W1a[4], W1b[4], W2a[4], W2b[4];
    float a2[4], vi2[4], N1n[4], aT[4];
    #pragma unroll
    for (int q = 0; q < 4; q++) {
        int c = tid + q * 256;
        a[q]  = sigmoidf_acc(lam[c]); vi[q] = vv[c]; uo[q] = uu[c];
        N1[q] = n1w[c]; N2[q] = n2w[c];
        W1a[q] = w1[2 * c]; W1b[q] = w1[2 * c + 1];
        W2a[q] = w2[c];     W2b[q] = w2[DD + c];
        a2[q] = sigmoidf_acc(lam_n[c]); vi2[q] = vv_n[c]; N1n[q] = n1w_n[c];
        float t = a[q]; t *= t; t *= t; t *= t; aT[q] = t;   // a^8 = a^TC
    }

    // ---- decoupled look-back: h_in(ch) = affine-prefix over chunks < ch ----
    float hin[4] = {0.f, 0.f, 0.f, 0.f};
    {
        float wgt[4] = {1.f, 1.f, 1.f, 1.f};
        int j = ch - 1;
        bool done = (ch == 0);
        while (!done) {
            if (tid == 0) {
                int mode; long spins = 0;
                for (;;) {
                    unsigned pf = *(volatile unsigned*)&g_pflag[b * NCH + j];
                    if (pf >= Vt) { mode = 1; break; }
                    unsigned af = *(volatile unsigned*)&g_aflag[p][b * NCH + j];
                    if (af >= Vt) { mode = 0; break; }
                    __nanosleep(64);
                    if (++spins > 5000000L) { mode = 2; break; }  // diagnosable give-up
                }
                __threadfence();
                s_mode = mode;
            }
            __syncthreads();
            int mode = s_mode;
            __syncthreads();
            if (mode == 1) {
                const float* hp = g_HIN + (size_t)(b * NCH + j) * DD;
                #pragma unroll
                for (int q = 0; q < 4; q++) hin[q] += wgt[q] * hp[tid + q * 256];
                done = true;
            } else if (mode == 0) {
                const float* bp = g_HLOCp[p] + (size_t)(b * NCH + j) * DD;
                #pragma unroll
                for (int q = 0; q < 4; q++) {
                    hin[q] += wgt[q] * bp[tid + q * 256];
                    wgt[q] *= aT[q];
                }
                if (--j < 0) done = true;
            } else {
                done = true;   // spin cap hit -> wrong result (diagnosable, no hang)
            }
        }
    }

    // ---- publish inclusive prefix: HINC = aT*h_in + B(own) ----
    {
        const float* bp = g_HLOCp[p] + (size_t)myIdx * DD;
        float* ip = g_HIN + (size_t)myIdx * DD;
        #pragma unroll
        for (int q = 0; q < 4; q++)
            ip[tid + q * 256] = aT[q] * hin[q] + bp[tid + q * 256];
    }
    __syncthreads();
    if (tid == 0) {
        __threadfence();
        *(volatile unsigned*)&g_pflag[myIdx] = Vt;
    }

    // quadratic sums of w2 rows (algebraic second rmsnorm)
    float Qaa, Qbb, Qab;
    {
        float pr[5] = {0.f, 0.f, 0.f, 0.f, 0.f};
        #pragma unroll
        for (int q = 0; q < 4; q++) {
            pr[0] += W2a[q] * W2a[q];
            pr[1] += W2b[q] * W2b[q];
            pr[2] += W2a[q] * W2b[q];
        }
        blockReduce5(pr, sbuf);
        Qaa = pr[0]; Qbb = pr[1]; Qab = pr[2];
    }

    // bulk-load all 8 rows + rms factors
    float x[TC][4], rr[TC];
    #pragma unroll
    for (int t = 0; t < TC; t++) {
        const float* xr = g_X + (size_t)(row0 + t) * DD;
        #pragma unroll
        for (int q = 0; q < 4; q++) x[t][q] = xr[tid + q * 256];
    }
    #pragma unroll
    for (int t = 0; t < TC; t++) rr[t] = g_R[row0 + t];

    // Phase A: serial scan from h_in + per-row warp partial reduce
    float h[4];
    #pragma unroll
    for (int q = 0; q < 4; q++) h[q] = hin[q];
    #pragma unroll
    for (int t = 0; t < TC; t++) {
        float pr[5] = {0.f, 0.f, 0.f, 0.f, 0.f};
        #pragma unroll
        for (int q = 0; q < 4; q++) {
            float z = x[t][q] * rr[t] * N1[q];
            h[q] = a[q] * h[q] + vi[q] * z;
            float xp = x[t][q] + uo[q] * h[q];
            x[t][q] = xp;
            pr[0] += xp * xp;
            float xw = xp * N2[q];
            pr[1] += xw * W1a[q];
            pr[2] += xw * W1b[q];
            pr[3] += xp * W2a[q];
            pr[4] += xp * W2b[q];
        }
        #pragma unroll
        for (int o = 16; o > 0; o >>= 1) {
            #pragma unroll
            for (int j = 0; j < 5; j++) pr[j] += __shfl_down_sync(0xffffffffu, pr[j], o);
        }
        if (lane == 0) {
            #pragma unroll
            for (int j = 0; j < 5; j++) sW[(t * 8 + w) * 5 + j] = pr[j];
        }
    }
    __syncthreads();

    // Phase B: warp w finalizes row w
    {
        float s = 0.f;
        if (lane < 5) {
            #pragma unroll
            for (int k = 0; k < 8; k++) s += sW[(w * 8 + k) * 5 + lane];
        }
        float p0 = __shfl_sync(0xffffffffu, s, 0);
        float p1 = __shfl_sync(0xffffffffu, s, 1);
        float p2 = __shfl_sync(0xffffffffu, s, 2);
        float p3 = __shfl_sync(0xffffffffu, s, 3);
        float p4 = __shfl_sync(0xffffffffu, s, 4);
        float r2 = rsqrtf(p0 * (1.f / (float)DD) + EPSF);
        float g0 = geluf(r2 * p1);
        float g1 = geluf(r2 * p2);
        float sf = p0 + 2.f * (g0 * p3 + g1 * p4)
                 + g0 * g0 * Qaa + g1 * g1 * Qbb + 2.f * g0 * g1 * Qab;
        float rnext = rsqrtf(sf * (1.f / (float)DD) + EPSF);
        if (lane == 0) {
            sS[w * 4 + 0] = g0; sS[w * 4 + 1] = g1; sS[w * 4 + 2] = rnext;
            g_R[row0 + w] = rnext;
        }
    }
    __syncthreads();

    // Phase C: FFN apply + store + next-layer partial scan -> HLOC parity pn
    float h2[4] = {0.f, 0.f, 0.f, 0.f};
    #pragma unroll
    for (int t = 0; t < TC; t++) {
        float g0 = sS[t * 4 + 0], g1 = sS[t * 4 + 1], rn = sS[t * 4 + 2];
        float* xo = g_X + (size_t)(row0 + t) * DD;
        #pragma unroll
        for (int q = 0; q < 4; q++) {
            float xf = x[t][q] + g0 * W2a[q] + g1 * W2b[q];
            xo[tid + q * 256] = xf;
            if (!last) {
                float z2 = xf * rn * N1n[q];
                h2[q] = a2[q] * h2[q] + vi2[q] * z2;
            }
        }
    }
    if (!last) {
        #pragma unroll
        for (int q = 0; q < 4; q++)
            g_HLOCp[pn][(size_t)myIdx * DD + tid + q * 256] = h2[q];
        __syncthreads();
        if (tid == 0) {
            __threadfence();
            *(volatile unsigned*)&g_aflag[pn][myIdx] = Vtn;
        }
    }
}

// ============================================================
// 3) final TT-factored output projection (round-10 proven version)
// ============================================================
#define PROJ_SMEM_BYTES (17760 * 4)
__global__ void __launch_bounds__(256) k_proj(const float* __restrict__ c1,
                                              const float* __restrict__ c2,
                                              const float* __restrict__ fnw,
                                              float* __restrict__ out) {
    extern __shared__ float sm[];
    float* sXF  = sm;                  // [32][34]
    float* sC2  = sm + 1088;           // [160][32]
    float* sT   = sm + 6208;           // [32][161] plain float
    ull*   sC1q = (ull*)(sm + 11360);  // [v1g][k][i] pre-paired

    int row = blockIdx.x, tid = threadIdx.x;
    const float* xr = g_X + (size_t)row * DD;
    float r = g_R[row];

    #pragma unroll
    for (int q = 0; q < 4; q++) {
        int d = tid + q * 256; int d1 = d >> 5, d2 = d & 31;
        sXF[d1 * 34 + d2] = xr[d] * r * fnw[d];
    }
    for (int i = tid; i < NV2 * 32; i += 256) sC2[i] = c2[i];
    for (int i = tid; i < 100 * 32; i += 256) {
        int p = i >> 5, k = i & 31;
        int v1g = p >> 2, ii = p & 3;
        float lo = c1[(2 * p) * 32 + k];
        float hi = c1[(2 * p + 1) * 32 + k];
        sC1q[(v1g * 32 + k) * 4 + ii] = pack2(lo, hi);
    }
    __syncthreads();

    {
        int d1 = tid & 31;
        int v2b = (tid >> 5) * 20;
        const ull* xfp = (const ull*)(sXF + d1 * 34);
        ull xreg[16];
        #pragma unroll
        for (int kk = 0; kk < 16; kk++) xreg[kk] = xfp[kk];
        for (int n = 0; n < 20; n++) {
            int v2 = v2b + n;
            const ulonglong2* c2q = (const ulonglong2*)(sC2 + v2 * 32);
            ull acc = 0ull;
            #pragma unroll
            for (int kk = 0; kk < 8; kk++) {
                ulonglong2 cc = c2q[kk];
                acc = ffma2(xreg[2 * kk],     cc.x, acc);
                acc = ffma2(xreg[2 * kk + 1], cc.y, acc);
            }
            float lo, hi; unpack2(acc, lo, hi);
            sT[d1 * 161 + v2] = lo + hi;
        }
    }
    __syncthreads();

    float* orow = out + (size_t)row * (NV1 * NV2);
    for (int it = 0; it < 4; it++) {
        int tile = it * 256 + tid;
        if (tile >= 800) break;
        int l = tile & 31, v1g = tile >> 5;
        const ulonglong2* c1p = (const ulonglong2*)(sC1q + v1g * 32 * 4);
        ull acc[4][5];
        #pragma unroll
        for (int i = 0; i < 4; i++)
            #pragma unroll
            for (int j = 0; j < 5; j++) acc[i][j] = 0ull;
        #pragma unroll 8
        for (int k = 0; k < 32; k++) {
            ulonglong2 q0 = c1p[2 * k];
            ulonglong2 q1 = c1p[2 * k + 1];
            ull cp[4] = {q0.x, q0.y, q1.x, q1.y};
            ull td[5];
            #pragma unroll
            for (int j = 0; j < 5; j++) {
                float t = sT[k * 161 + l + 32 * j];
                td[j] = pack2(t, t);
            }
            #pragma unroll
            for (int i = 0; i < 4; i++)
                #pragma unroll
                for (int j = 0; j < 5; j++) acc[i][j] = ffma2(cp[i], td[j], acc[i][j]);
        }
        #pragma unroll
        for (int i = 0; i < 4; i++) {
            int v1 = v1g * 8 + 2 * i;
            float* p0 = orow + v1 * NV2 + l;
            float* p1 = p0 + NV2;
            #pragma unroll
            for (int j = 0; j < 5; j++) {
                float lo, hi; unpack2(acc[i][j], lo, hi);
                p0[32 * j] = lo; p1[32 * j] = hi;
            }
        }
    }
}

// ============================================================
// launcher: 11 launches (was 18)
// ============================================================
extern "C" void kernel_launch(void* const* d_in, const int* in_sizes, int n_in,
                              void* d_out, int out_size) {
    const int*   ids   = (const int*)d_in[0];
    const float* core1 = (const float*)d_in[1];
    const float* core2 = (const float*)d_in[2];
    const float* lam   = (const float*)d_in[3];
    const float* uu    = (const float*)d_in[4];
    const float* vv    = (const float*)d_in[5];
    const float* w1    = (const float*)d_in[6];
    const float* w2    = (const float*)d_in[7];
    const float* n1w   = (const float*)d_in[8];
    const float* n2w   = (const float*)d_in[9];
    const float* fnw   = (const float*)d_in[10];
    float* out = (float*)d_out;

    cudaFuncSetAttribute(k_proj, cudaFuncAttributeMaxDynamicSharedMemorySize,
                         PROJ_SMEM_BYTES);

    k_epoch<<<1, 1>>>();
    k_embed_fused<<<BB * NCH, 256>>>(ids, core1, core2, lam, vv, n1w);

    for (int l = 0; l < NLAY; l++) {
        int ln = (l + 1 < NLAY) ? (l + 1) : l;
        int last = (l == NLAY - 1) ? 1 : 0;
        k_fused<<<BB * NCH, 256>>>(lam + l * DD, vv + l * DD, uu + l * DD,
                                   n1w + l * DD, n2w + l * DD,
                                   w1 + l * DD * 2, w2 + l * 2 * DD,
                                   lam + ln * DD, vv + ln * DD, n1w + ln * DD,
                                   l, last);
    }

    k_proj<<<NROWS, 256, PROJ_SMEM_BYTES>>>(core1, core2, fnw, out);
}

// round 15
// speedup vs baseline: 1.8842x; 1.8842x over previous
#include <cuda_runtime.h>
#include <cuda_bf16.h>

// ---- model constants ----
#define BB 2
#define SS 2048
#define DD 1024
#define NLAY 8
#define NV1 200
#define NV2 160
#define NCH 256       // scan chunks over S
#define TC 8          // timesteps per chunk (NCH*TC == SS)
#define NROWS (BB*SS) // 4096
#define EPSF 1e-6f

typedef unsigned long long ull;

// ---- device scratch (no allocations allowed) ----
__device__ float g_X[NROWS * DD];        // activations [B,S,D]  (16.8 MB, L2-resident)
__device__ float g_R[NROWS];             // per-row rmsnorm factors (current layer)
__device__ float g_HLOC[BB * NCH * DD];  // per-chunk local scan terminal state
__device__ float g_HIN[BB * NCH * DD];   // per-chunk incoming state

// ---- f32x2 packed-math helpers (2x fp32 FMA rate on sm_103a) ----
__device__ __forceinline__ ull pack2(float lo, float hi) {
    ull r; asm("mov.b64 %0, {%1, %2};" : "=l"(r) : "f"(lo), "f"(hi)); return r;
}
__device__ __forceinline__ void unpack2(ull v, float& lo, float& hi) {
    asm("mov.b64 {%0, %1}, %2;" : "=f"(lo), "=f"(hi) : "l"(v));
}
__device__ __forceinline__ ull ffma2(ull a, ull b, ull c) {
    ull d; asm("fma.rn.f32x2 %0, %1, %2, %3;" : "=l"(d) : "l"(a), "l"(b), "l"(c)); return d;
}

__device__ __forceinline__ float sigmoidf_acc(float x) { return 1.f / (1.f + expf(-x)); }

// jax.nn.gelu default = tanh approximation
__device__ __forceinline__ float geluf(float x) {
    float x3 = x * x * x;
    return 0.5f * x * (1.f + tanhf(0.7978845608028654f * (x + 0.044715f * x3)));
}

// 5-wide block reduce with broadcast; sbuf >= 48 floats (256 threads)
__device__ __forceinline__ void blockReduce5(float* p, float* sbuf) {
    int lane = threadIdx.x & 31, w = threadIdx.x >> 5;
    #pragma unroll
    for (int o = 16; o > 0; o >>= 1) {
        #pragma unroll
        for (int j = 0; j < 5; j++) p[j] += __shfl_down_sync(0xffffffffu, p[j], o);
    }
    if (lane == 0) {
        #pragma unroll
        for (int j = 0; j < 5; j++) sbuf[w * 5 + j] = p[j];
    }
    __syncthreads();
    if (w == 0) {
        float q[5];
        #pragma unroll
        for (int j = 0; j < 5; j++) q[j] = (lane < 8) ? sbuf[lane * 5 + j] : 0.f;
        #pragma unroll
        for (int o = 4; o > 0; o >>= 1) {
            #pragma unroll
            for (int j = 0; j < 5; j++) q[j] += __shfl_down_sync(0xffffffffu, q[j], o);
        }
        if (lane == 0) {
            #pragma unroll
            for (int j = 0; j < 5; j++) sbuf[40 + j] = q[j];
        }
    }
    __syncthreads();
    #pragma unroll
    for (int j = 0; j < 5; j++) p[j] = sbuf[40 + j];
}

// ============================================================
// 1) fused embed: TT embedding + rmsnorm factor + layer-0 partial scan
// ============================================================
__global__ void __launch_bounds__(256) k_embed_fused(
        const int* __restrict__ ids,
        const float* __restrict__ c1,
        const float* __restrict__ c2,
        const float* __restrict__ lam0,
        const float* __restrict__ vv0,
        const float* __restrict__ n1w0) {
    __shared__ float s1[TC][32], s2[TC][32];
    __shared__ float sW[TC * 8];   // per-row per-warp partial sums
    __shared__ float sR[TC];
    int blk = blockIdx.x; int b = blk >> 8; int ch = blk & (NCH - 1);
    int tid = threadIdx.x, lane = tid & 31, w = tid >> 5;
    int row0 = b * SS + ch * TC;

    float a[4], vi[4], N1[4];
    #pragma unroll
    for (int q = 0; q < 4; q++) {
        int c = tid + q * 256;
        a[q] = sigmoidf_acc(lam0[c]); vi[q] = vv0[c]; N1[q] = n1w0[c];
    }

    // stage TT cores for all 8 rows
    for (int i = tid; i < TC * 64; i += 256) {
        int t = i >> 6, j = i & 63;
        int id = ids[row0 + t];
        if (j < 32) s1[t][j] = c1[(id / NV2) * 32 + j];
        else        s2[t][j - 32] = c2[(id % NV2) * 32 + (j - 32)];
    }
    __syncthreads();

    float x[TC][4];
    #pragma unroll
    for (int t = 0; t < TC; t++) {
        float s = 0.f;
        #pragma unroll
        for (int q = 0; q < 4; q++) {
            int d = tid + q * 256;
            x[t][q] = s1[t][d >> 5] * s2[t][d & 31];
            s += x[t][q] * x[t][q];
        }
        #pragma unroll
        for (int o = 16; o > 0; o >>= 1) s += __shfl_down_sync(0xffffffffu, s, o);
        if (lane == 0) sW[t * 8 + w] = s;
        float* xr = g_X + (size_t)(row0 + t) * DD;
        #pragma unroll
        for (int q = 0; q < 4; q++) xr[tid + q * 256] = x[t][q];
    }
    __syncthreads();

    // warp w finalizes row w's rms factor
    {
        float s = (lane < 8) ? sW[w * 8 + lane] : 0.f;
        #pragma unroll
        for (int o = 4; o > 0; o >>= 1) s += __shfl_down_sync(0xffffffffu, s, o);
        float tot = __shfl_sync(0xffffffffu, s, 0);
        float r = rsqrtf(tot * (1.f / (float)DD) + EPSF);
        if (lane == 0) { sR[w] = r; g_R[row0 + w] = r; }
    }
    __syncthreads();

    // layer-0 partial scan (h0 = 0)
    float h[4] = {0.f, 0.f, 0.f, 0.f};
    #pragma unroll
    for (int t = 0; t < TC; t++) {
        float r = sR[t];
        #pragma unroll
        for (int q = 0; q < 4; q++) {
            float z = x[t][q] * r * N1[q];
            h[q] = a[q] * h[q] + vi[q] * z;
        }
    }
    size_t hidx = (size_t)(b * NCH + ch) * DD;
    #pragma unroll
    for (int q = 0; q < 4; q++) g_HLOC[hidx + tid + q * 256] = h[q];
}

// ============================================================
// 2) scan combine: 256 blocks, 8 channels/block, 1 channel PER WARP.
// ============================================================
__global__ void __launch_bounds__(256) k_combine(const float* __restrict__ lam) {
    __shared__ float sH[NCH * 9];            // [chunk][8 channels] pitch 9
    int g = blockIdx.x;                      // 0..255
    int b = g >> 7;                          // 0..1
    int c0 = (g & 127) * 8;                  // 8-channel slice
    int tid = threadIdx.x, lane = tid & 31, w = tid >> 5;

    for (int i = tid; i < NCH * 8; i += 256) {
        int k = i >> 3, cl = i & 7;
        sH[k * 9 + cl] = g_HLOC[(size_t)(b * NCH + k) * DD + c0 + cl];
    }
    __syncthreads();

    {
        int cl = w;
        int c = c0 + cl;
        float av = sigmoidf_acc(lam[c]);
        float aT = av; aT *= aT; aT *= aT; aT *= aT;   // a^8 = a^TC
        float m0 = aT, m1 = m0 * m0, m2 = m1 * m1, m3 = m2 * m2, m4 = m3 * m3;
        float pw = 1.f;
        if (lane & 1)  pw *= m0;
        if (lane & 2)  pw *= m1;
        if (lane & 4)  pw *= m2;
        if (lane & 8)  pw *= m3;
        if (lane & 16) pw *= m4;
        float aT32 = m4 * m4;

        float carry = 0.f;
        #pragma unroll
        for (int j = 0; j < 8; j++) {
            int k = j * 32 + lane;
            float B = sH[k * 9 + cl];
            float t;
            t = __shfl_up_sync(0xffffffffu, B, 1);  if (lane >= 1)  B += m0 * t;
            t = __shfl_up_sync(0xffffffffu, B, 2);  if (lane >= 2)  B += m1 * t;
            t = __shfl_up_sync(0xffffffffu, B, 4);  if (lane >= 4)  B += m2 * t;
            t = __shfl_up_sync(0xffffffffu, B, 8);  if (lane >= 8)  B += m3 * t;
            t = __shfl_up_sync(0xffffffffu, B, 16); if (lane >= 16) B += m4 * t;
            float ex = __shfl_up_sync(0xffffffffu, B, 1);
            if (lane == 0) ex = 0.f;
            float hin = pw * carry + ex;
            float last = __shfl_sync(0xffffffffu, B, 31);
            sH[k * 9 + cl] = hin;
            carry = aT32 * carry + last;
        }
    }
    __syncthreads();

    for (int i = tid; i < NCH * 8; i += 256) {
        int k = i >> 3, cl = i & 7;
        g_HIN[(size_t)(b * NCH + k) * DD + c0 + cl] = sH[k * 9 + cl];
    }
}

// ============================================================
// 3) fused layer kernel: scan-apply(l) + FFN(l) + next-layer rms (algebraic)
//    + next-layer partial scan.
// ============================================================
__global__ void __launch_bounds__(256) k_fused(
        const float* __restrict__ lam, const float* __restrict__ vv,
        const float* __restrict__ uu,  const float* __restrict__ n1w,
        const float* __restrict__ n2w, const float* __restrict__ w1,
        const float* __restrict__ w2,
        const float* __restrict__ lam_n, const float* __restrict__ vv_n,
        const float* __restrict__ n1w_n, int last) {
    __shared__ float sbuf[48];
    __shared__ float sW[TC * 8 * 5];  // [row][warp][5]
    __shared__ float sS[TC * 4];      // [row]{g0,g1,rnext}
    int blk = blockIdx.x; int b = blk >> 8; int ch = blk & (NCH - 1);
    int tid = threadIdx.x, lane = tid & 31, w = tid >> 5;
    size_t hidx = (size_t)(b * NCH + ch) * DD;
    int row0 = b * SS + ch * TC;

    float a[4], vi[4], uo[4], N1[4], N2[4], W1a[4], W1b[4], W2a[4], W2b[4];
    float a2[4], vi2[4], N1n[4], h[4], h2[4];
    #pragma unroll
    for (int q = 0; q < 4; q++) {
        int c = tid + q * 256;
        a[q]  = sigmoidf_acc(lam[c]); vi[q] = vv[c]; uo[q] = uu[c];
        N1[q] = n1w[c]; N2[q] = n2w[c];
        W1a[q] = w1[2 * c]; W1b[q] = w1[2 * c + 1];
        W2a[q] = w2[c];     W2b[q] = w2[DD + c];
        h[q] = g_HIN[hidx + c];
        h2[q] = 0.f;
        a2[q] = sigmoidf_acc(lam_n[c]); vi2[q] = vv_n[c]; N1n[q] = n1w_n[c];
    }

    // quadratic sums of w2 rows (algebraic second rmsnorm)
    float Qaa, Qbb, Qab;
    {
        float p[5] = {0.f, 0.f, 0.f, 0.f, 0.f};
        #pragma unroll
        for (int q = 0; q < 4; q++) {
            p[0] += W2a[q] * W2a[q];
            p[1] += W2b[q] * W2b[q];
            p[2] += W2a[q] * W2b[q];
        }
        blockReduce5(p, sbuf);
        Qaa = p[0]; Qbb = p[1]; Qab = p[2];
    }

    // bulk-load all 8 rows (MLP=32) + rms factors
    float x[TC][4], rr[TC];
    #pragma unroll
    for (int t = 0; t < TC; t++) {
        const float* xr = g_X + (size_t)(row0 + t) * DD;
        #pragma unroll
        for (int q = 0; q < 4; q++) x[t][q] = xr[tid + q * 256];
    }
    #pragma unroll
    for (int t = 0; t < TC; t++) rr[t] = g_R[row0 + t];

    // Phase A: serial scan + per-row warp partial reduce
    #pragma unroll
    for (int t = 0; t < TC; t++) {
        float p[5] = {0.f, 0.f, 0.f, 0.f, 0.f};
        #pragma unroll
        for (int q = 0; q < 4; q++) {
            float z = x[t][q] * rr[t] * N1[q];
            h[q] = a[q] * h[q] + vi[q] * z;
            float xp = x[t][q] + uo[q] * h[q];
            x[t][q] = xp;
            p[0] += xp * xp;
            float xw = xp * N2[q];
            p[1] += xw * W1a[q];
            p[2] += xw * W1b[q];
            p[3] += xp * W2a[q];
            p[4] += xp * W2b[q];
        }
        #pragma unroll
        for (int o = 16; o > 0; o >>= 1) {
            #pragma unroll
            for (int j = 0; j < 5; j++) p[j] += __shfl_down_sync(0xffffffffu, p[j], o);
        }
        if (lane == 0) {
            #pragma unroll
            for (int j = 0; j < 5; j++) sW[(t * 8 + w) * 5 + j] = p[j];
        }
    }
    __syncthreads();

    // Phase B: warp w finalizes row w
    {
        float s = 0.f;
        if (lane < 5) {
            #pragma unroll
            for (int k = 0; k < 8; k++) s += sW[(w * 8 + k) * 5 + lane];
        }
        float p0 = __shfl_sync(0xffffffffu, s, 0);
        float p1 = __shfl_sync(0xffffffffu, s, 1);
        float p2 = __shfl_sync(0xffffffffu, s, 2);
        float p3 = __shfl_sync(0xffffffffu, s, 3);
        float p4 = __shfl_sync(0xffffffffu, s, 4);
        float r2 = rsqrtf(p0 * (1.f / (float)DD) + EPSF);
        float g0 = geluf(r2 * p1);
        float g1 = geluf(r2 * p2);
        float sf = p0 + 2.f * (g0 * p3 + g1 * p4)
                 + g0 * g0 * Qaa + g1 * g1 * Qbb + 2.f * g0 * g1 * Qab;
        float rnext = rsqrtf(sf * (1.f / (float)DD) + EPSF);
        if (lane == 0) {
            sS[w * 4 + 0] = g0; sS[w * 4 + 1] = g1; sS[w * 4 + 2] = rnext;
            g_R[row0 + w] = rnext;
        }
    }
    __syncthreads();

    // Phase C: FFN apply + store + next-layer partial scan
    #pragma unroll
    for (int t = 0; t < TC; t++) {
        float g0 = sS[t * 4 + 0], g1 = sS[t * 4 + 1], rn = sS[t * 4 + 2];
        float* xo = g_X + (size_t)(row0 + t) * DD;
        #pragma unroll
        for (int q = 0; q < 4; q++) {
            float xf = x[t][q] + g0 * W2a[q] + g1 * W2b[q];
            xo[tid + q * 256] = xf;
            if (!last) {
                float z2 = xf * rn * N1n[q];
                h2[q] = a2[q] * h2[q] + vi2[q] * z2;
            }
        }
    }
    if (!last) {
        #pragma unroll
        for (int q = 0; q < 4; q++) g_HLOC[hidx + tid + q * 256] = h2[q];
    }
}

// ============================================================
// 4) final TT-factored output projection — 2 ROWS PER BLOCK.
//    Weight staging (c1, c2) and stage sync amortized over 2 rows;
//    stage-2 accumulators remain single-row (register-safe).
// smem (floats):
//   sXF  [2][32][34]         @ 0      (2176)
//   sC2  [160][32]           @ 2176   (5120)
//   sT   [2][32][161]        @ 7296   (10304)
//   sC1q ull[25][32][4]      @ 17600  (6400 floats, 8B aligned)
// total 24000 floats = 96000 B -> 2 blocks/SM
// ============================================================
#define PROJ_SMEM_BYTES (24000 * 4)
__global__ void __launch_bounds__(256) k_proj(const float* __restrict__ c1,
                                              const float* __restrict__ c2,
                                              const float* __restrict__ fnw,
                                              float* __restrict__ out) {
    extern __shared__ float sm[];
    float* sXF  = sm;                  // [2][32][34]
    float* sC2  = sm + 2176;           // [160][32]
    float* sT   = sm + 7296;           // [2][32][161]
    ull*   sC1q = (ull*)(sm + 17600);  // [v1g][k][i] pre-paired

    int row0 = blockIdx.x * 2, tid = threadIdx.x;

    // stage xf for both rows
    #pragma unroll
    for (int rs = 0; rs < 2; rs++) {
        const float* xr = g_X + (size_t)(row0 + rs) * DD;
        float r = g_R[row0 + rs];
        #pragma unroll
        for (int q = 0; q < 4; q++) {
            int d = tid + q * 256; int d1 = d >> 5, d2 = d & 31;
            sXF[rs * 1088 + d1 * 34 + d2] = xr[d] * r * fnw[d];
        }
    }
    // stage weights (once per block, amortized over 2 rows)
    for (int i = tid; i < NV2 * 32; i += 256) sC2[i] = c2[i];
    for (int i = tid; i < 100 * 32; i += 256) {
        int p = i >> 5, k = i & 31;          // p = v1 pair index 0..99
        int v1g = p >> 2, ii = p & 3;
        float lo = c1[(2 * p) * 32 + k];
        float hi = c1[(2 * p + 1) * 32 + k];
        sC1q[(v1g * 32 + k) * 4 + ii] = pack2(lo, hi);
    }
    __syncthreads();

    // ---- stage 1 (both rows): thread owns d1 = tid&31, 20 v2's ----
    #pragma unroll
    for (int rs = 0; rs < 2; rs++) {
        int d1 = tid & 31;
        int v2b = (tid >> 5) * 20;
        const ull* xfp = (const ull*)(sXF + rs * 1088 + d1 * 34);
        ull xreg[16];
        #pragma unroll
        for (int kk = 0; kk < 16; kk++) xreg[kk] = xfp[kk];
        for (int n = 0; n < 20; n++) {
            int v2 = v2b + n;
            const ulonglong2* c2q = (const ulonglong2*)(sC2 + v2 * 32);
            ull acc = 0ull;
            #pragma unroll
            for (int kk = 0; kk < 8; kk++) {
                ulonglong2 cc = c2q[kk];                 // 16B uniform broadcast
                acc = ffma2(xreg[2 * kk],     cc.x, acc);
                acc = ffma2(xreg[2 * kk + 1], cc.y, acc);
            }
            float lo, hi; unpack2(acc, lo, hi);
            sT[rs * 5152 + d1 * 161 + v2] = lo + hi;
        }
    }
    __syncthreads();

    // ---- stage 2: 1600 tiles (2 rows x 25 v1-groups x 32 lanes) ----
    for (int it = 0; it < 7; it++) {
        int tile = it * 256 + tid;
        if (tile >= 1600) break;
        int rs = (tile >= 800) ? 1 : 0;
        int tt = tile - rs * 800;
        int l = tt & 31, v1g = tt >> 5;
        const float* sTr = sT + rs * 5152;
        const ulonglong2* c1p = (const ulonglong2*)(sC1q + v1g * 32 * 4);
        ull acc[4][5];
        #pragma unroll
        for (int i = 0; i < 4; i++)
            #pragma unroll
            for (int j = 0; j < 5; j++) acc[i][j] = 0ull;
        #pragma unroll 8
        for (int k = 0; k < 32; k++) {
            ulonglong2 q0 = c1p[2 * k];          // pairs i=0,1 (uniform LDS.128)
            ulonglong2 q1 = c1p[2 * k + 1];      // pairs i=2,3
            ull cp[4] = {q0.x, q0.y, q1.x, q1.y};
            ull td[5];
            #pragma unroll
            for (int j = 0; j < 5; j++) {
                float t = sTr[k * 161 + l + 32 * j];  // LDS.32, 1 wavefront
                td[j] = pack2(t, t);                   // ALU pipe
            }
            #pragma unroll
            for (int i = 0; i < 4; i++)
                #pragma unroll
                for (int j = 0; j < 5; j++) acc[i][j] = ffma2(cp[i], td[j], acc[i][j]);
        }
        float* orow = out + (size_t)(row0 + rs) * (NV1 * NV2);
        #pragma unroll
        for (int i = 0; i < 4; i++) {
            int v1 = v1g * 8 + 2 * i;
            float* p0 = orow + v1 * NV2 + l;
            float* p1 = p0 + NV2;
            #pragma unroll
            for (int j = 0; j < 5; j++) {
                float lo, hi; unpack2(acc[i][j], lo, hi);
                p0[32 * j] = lo; p1[32 * j] = hi;    // coalesced per (i,j)
            }
        }
    }
}

// ============================================================
// launcher
// ============================================================
extern "C" void kernel_launch(void* const* d_in, const int* in_sizes, int n_in,
                              void* d_out, int out_size) {
    const int*   ids   = (const int*)d_in[0];
    const float* core1 = (const float*)d_in[1];
    const float* core2 = (const float*)d_in[2];
    const float* lam   = (const float*)d_in[3];
    const float* uu    = (const float*)d_in[4];
    const float* vv    = (const float*)d_in[5];
    const float* w1    = (const float*)d_in[6];
    const float* w2    = (const float*)d_in[7];
    const float* n1w   = (const float*)d_in[8];
    const float* n2w   = (const float*)d_in[9];
    const float* fnw   = (const float*)d_in[10];
    float* out = (float*)d_out;

    cudaFuncSetAttribute(k_proj, cudaFuncAttributeMaxDynamicSharedMemorySize,
                         PROJ_SMEM_BYTES);

    // embed + layer-0 rms + layer-0 partial scan
    k_embed_fused<<<BB * NCH, 256>>>(ids, core1, core2, lam, vv, n1w);

    for (int l = 0; l < NLAY; l++) {
        int ln = (l + 1 < NLAY) ? (l + 1) : l;   // dummy (guarded) for last layer
        int last = (l == NLAY - 1) ? 1 : 0;
        k_combine<<<256, 256>>>(lam + l * DD);
        k_fused<<<BB * NCH, 256>>>(lam + l * DD, vv + l * DD, uu + l * DD,
                                   n1w + l * DD, n2w + l * DD,
                                   w1 + l * DD * 2, w2 + l * 2 * DD,
                                   lam + ln * DD, vv + ln * DD, n1w + ln * DD,
                                   last);
    }

    k_proj<<<NROWS / 2, 256, PROJ_SMEM_BYTES>>>(core1, core2, fnw, out);
}